// round 3
// baseline (speedup 1.0000x reference)
#include <cuda_runtime.h>
#include <cuda_bf16.h>

#define N_NODES 100000
#define NFEAT   1433
#define NHID    40
#define NCLASS  7
#define NC_PAD  8

// ---------------- scratch (device globals; no allocation allowed) -------------
__device__ float g_sup1[N_NODES * NHID];   // x @ W1
__device__ float g_agg1[N_NODES * NHID];   // segment_sum layer 1
__device__ float g_h1  [N_NODES * NHID];   // relu+dropout output
__device__ float g_sup2[N_NODES * NC_PAD]; // h1 @ W2 (padded)
__device__ float g_agg2[N_NODES * NC_PAD]; // segment_sum layer 2 (padded)

// ---------------- helpers ----------------------------------------------------
__device__ __forceinline__ void red_add_v4(float* addr, float a, float b, float c, float d) {
    asm volatile("red.global.add.v4.f32 [%0], {%1, %2, %3, %4};"
                 :: "l"(addr), "f"(a), "f"(b), "f"(c), "f"(d) : "memory");
}

// ---------------- GEMM1: g_sup1 = x @ W1  (N x 1433 @ 1433 x 40) --------------
// Block: 256 threads, tile 128 rows x 40 cols, BK = 32.
// Thread (ty=tid/8 in 0..31, tx=tid%8 in 0..7) owns 4 rows x 5 cols.
__global__ void __launch_bounds__(256) gemm1_kernel(
    const float* __restrict__ x, const float* __restrict__ W1)
{
    __shared__ float xs[128][33];   // padded to kill bank conflicts
    __shared__ float ws[32][NHID];

    const int tid = threadIdx.x;
    const int ty  = tid >> 3;       // 0..31 -> row group (4 rows)
    const int tx  = tid & 7;        // 0..7  -> col group (5 cols)
    const int row0 = blockIdx.x * 128;

    float acc[4][5];
    #pragma unroll
    for (int i = 0; i < 4; i++)
        #pragma unroll
        for (int j = 0; j < 5; j++) acc[i][j] = 0.0f;

    for (int k0 = 0; k0 < NFEAT; k0 += 32) {
        // load x tile: 128 x 32 = 4096 elems, 16 per thread (coalesced in k)
        #pragma unroll
        for (int i = 0; i < 16; i++) {
            int idx = tid + i * 256;
            int r = idx >> 5, k = idx & 31;
            int gr = row0 + r, gk = k0 + k;
            float v = 0.0f;
            if (gr < N_NODES && gk < NFEAT) v = x[(long long)gr * NFEAT + gk];
            xs[r][k] = v;
        }
        // load W1 tile: 32 x 40 = 1280 elems, 5 per thread
        #pragma unroll
        for (int i = 0; i < 5; i++) {
            int idx = tid + i * 256;
            int k = idx / NHID, c = idx % NHID;
            int gk = k0 + k;
            ws[k][c] = (gk < NFEAT) ? W1[gk * NHID + c] : 0.0f;
        }
        __syncthreads();

        #pragma unroll
        for (int k = 0; k < 32; k++) {
            float a0 = xs[ty * 4 + 0][k];
            float a1 = xs[ty * 4 + 1][k];
            float a2 = xs[ty * 4 + 2][k];
            float a3 = xs[ty * 4 + 3][k];
            float b0 = ws[k][tx * 5 + 0];
            float b1 = ws[k][tx * 5 + 1];
            float b2 = ws[k][tx * 5 + 2];
            float b3 = ws[k][tx * 5 + 3];
            float b4 = ws[k][tx * 5 + 4];
            acc[0][0] += a0 * b0; acc[0][1] += a0 * b1; acc[0][2] += a0 * b2; acc[0][3] += a0 * b3; acc[0][4] += a0 * b4;
            acc[1][0] += a1 * b0; acc[1][1] += a1 * b1; acc[1][2] += a1 * b2; acc[1][3] += a1 * b3; acc[1][4] += a1 * b4;
            acc[2][0] += a2 * b0; acc[2][1] += a2 * b1; acc[2][2] += a2 * b2; acc[2][3] += a2 * b3; acc[2][4] += a2 * b4;
            acc[3][0] += a3 * b0; acc[3][1] += a3 * b1; acc[3][2] += a3 * b2; acc[3][3] += a3 * b3; acc[3][4] += a3 * b4;
        }
        __syncthreads();
    }

    #pragma unroll
    for (int i = 0; i < 4; i++) {
        int gr = row0 + ty * 4 + i;
        if (gr < N_NODES) {
            #pragma unroll
            for (int j = 0; j < 5; j++)
                g_sup1[gr * NHID + tx * 5 + j] = acc[i][j];
        }
    }
}

// ---------------- scatter layer 1: agg1[dst] += sup1[src] * w ----------------
__global__ void scatter1_kernel(const int* __restrict__ src, const int* __restrict__ dst,
                                const float* __restrict__ ew, int E)
{
    int e = blockIdx.x * blockDim.x + threadIdx.x;
    if (e >= E) return;
    int s = src[e], d = dst[e];
    float w = ew[e];
    const float4* sp = (const float4*)(g_sup1 + (long long)s * NHID);
    float*        ap = g_agg1 + (long long)d * NHID;
    #pragma unroll
    for (int c = 0; c < NHID / 4; c++) {
        float4 v = __ldg(sp + c);
        red_add_v4(ap + c * 4, v.x * w, v.y * w, v.z * w, v.w * w);
    }
}

// ---------------- relu(agg1 + b1) * dropout ----------------------------------
__global__ void relu_drop_kernel(const float* __restrict__ b1, const float* __restrict__ mask)
{
    int idx = blockIdx.x * blockDim.x + threadIdx.x;
    if (idx >= N_NODES * NHID) return;
    float v = g_agg1[idx] + __ldg(b1 + (idx % NHID));
    v = v > 0.0f ? v : 0.0f;
    g_h1[idx] = (__ldg(mask + idx) > 0.5f) ? v * 2.0f : 0.0f;
}

// ---------------- GEMM2: sup2 = h1 @ W2 (N x 40 @ 40 x 7, padded to 8) -------
__global__ void __launch_bounds__(256) gemm2_kernel(const float* __restrict__ W2)
{
    __shared__ float w2s[NHID * NCLASS];
    // NHID*NCLASS = 280 > blockDim (256): strided loop, NOT a single guarded store
    for (int i = threadIdx.x; i < NHID * NCLASS; i += 256) w2s[i] = W2[i];
    __syncthreads();

    int n = blockIdx.x * blockDim.x + threadIdx.x;
    if (n >= N_NODES) return;

    const float4* hp = (const float4*)(g_h1 + (long long)n * NHID);
    float h[NHID];
    #pragma unroll
    for (int i = 0; i < NHID / 4; i++) {
        float4 v = hp[i];
        h[i * 4 + 0] = v.x; h[i * 4 + 1] = v.y; h[i * 4 + 2] = v.z; h[i * 4 + 3] = v.w;
    }
    float acc[NCLASS];
    #pragma unroll
    for (int c = 0; c < NCLASS; c++) acc[c] = 0.0f;
    #pragma unroll
    for (int k = 0; k < NHID; k++) {
        float hv = h[k];
        #pragma unroll
        for (int c = 0; c < NCLASS; c++) acc[c] += hv * w2s[k * NCLASS + c];
    }
    float* op = g_sup2 + (long long)n * NC_PAD;
    #pragma unroll
    for (int c = 0; c < NCLASS; c++) op[c] = acc[c];
    op[NCLASS] = 0.0f;  // pad
}

// ---------------- scatter layer 2: agg2[dst] += sup2[src] * w ----------------
__global__ void scatter2_kernel(const int* __restrict__ src, const int* __restrict__ dst,
                                const float* __restrict__ ew, int E)
{
    int e = blockIdx.x * blockDim.x + threadIdx.x;
    if (e >= E) return;
    int s = src[e], d = dst[e];
    float w = ew[e];
    const float4* sp = (const float4*)(g_sup2 + (long long)s * NC_PAD);
    float*        ap = g_agg2 + (long long)d * NC_PAD;
    float4 v0 = __ldg(sp + 0);
    float4 v1 = __ldg(sp + 1);
    red_add_v4(ap + 0, v0.x * w, v0.y * w, v0.z * w, v0.w * w);
    red_add_v4(ap + 4, v1.x * w, v1.y * w, v1.z * w, v1.w * w);
}

// ---------------- log_softmax(agg2 + b2) -> out ------------------------------
__global__ void logsoftmax_kernel(const float* __restrict__ b2, float* __restrict__ out)
{
    int n = blockIdx.x * blockDim.x + threadIdx.x;
    if (n >= N_NODES) return;
    const float* ap = g_agg2 + (long long)n * NC_PAD;
    float z[NCLASS];
    float m = -1e30f;
    #pragma unroll
    for (int c = 0; c < NCLASS; c++) {
        z[c] = ap[c] + __ldg(b2 + c);
        m = fmaxf(m, z[c]);
    }
    float s = 0.0f;
    #pragma unroll
    for (int c = 0; c < NCLASS; c++) s += __expf(z[c] - m);
    float lse = m + __logf(s);
    #pragma unroll
    for (int c = 0; c < NCLASS; c++) out[n * NCLASS + c] = z[c] - lse;
}

// ---------------- launch -----------------------------------------------------
extern "C" void kernel_launch(void* const* d_in, const int* in_sizes, int n_in,
                              void* d_out, int out_size)
{
    const float* x    = (const float*)d_in[0];
    const int*   src  = (const int*)  d_in[1];
    const int*   dst  = (const int*)  d_in[2];
    const float* ew   = (const float*)d_in[3];
    const float* W1   = (const float*)d_in[4];
    const float* b1   = (const float*)d_in[5];
    const float* W2   = (const float*)d_in[6];
    const float* b2   = (const float*)d_in[7];
    const float* mask = (const float*)d_in[8];
    float* out = (float*)d_out;

    const int E = in_sizes[1];

    void* agg1_ptr = nullptr;
    void* agg2_ptr = nullptr;
    cudaGetSymbolAddress(&agg1_ptr, g_agg1);
    cudaGetSymbolAddress(&agg2_ptr, g_agg2);
    cudaMemsetAsync(agg1_ptr, 0, (size_t)N_NODES * NHID * sizeof(float), 0);
    cudaMemsetAsync(agg2_ptr, 0, (size_t)N_NODES * NC_PAD * sizeof(float), 0);

    gemm1_kernel<<<(N_NODES + 127) / 128, 256>>>(x, W1);
    scatter1_kernel<<<(E + 255) / 256, 256>>>(src, dst, ew, E);
    relu_drop_kernel<<<(N_NODES * NHID + 255) / 256, 256>>>(b1, mask);
    gemm2_kernel<<<(N_NODES + 255) / 256, 256>>>(W2);
    scatter2_kernel<<<(E + 255) / 256, 256>>>(src, dst, ew, E);
    logsoftmax_kernel<<<(N_NODES + 255) / 256, 256>>>(b2, out);
}

// round 4
// speedup vs baseline: 1.5955x; 1.5955x over previous
#include <cuda_runtime.h>
#include <cuda_bf16.h>

#define N_NODES 100000
#define NFEAT   1433
#define NHID    40
#define NCLASS  7
#define NC_PAD  8

typedef unsigned long long ull;

// ---------------- scratch (device globals; no allocation allowed) -------------
__device__ float g_sup1[N_NODES * NHID];   // x @ W1
__device__ float g_agg1[N_NODES * NHID];   // segment_sum layer 1
__device__ float g_sup2[N_NODES * NC_PAD]; // relu/drop -> @ W2 (padded)
__device__ float g_agg2[N_NODES * NC_PAD]; // segment_sum layer 2 (padded)

// ---------------- helpers ----------------------------------------------------
__device__ __forceinline__ void red_add_v4(float* addr, float a, float b, float c, float d) {
    asm volatile("red.global.add.v4.f32 [%0], {%1, %2, %3, %4};"
                 :: "l"(addr), "f"(a), "f"(b), "f"(c), "f"(d) : "memory");
}

__device__ __forceinline__ ull pack2(float lo, float hi) {
    ull r; asm("mov.b64 %0, {%1, %2};" : "=l"(r) : "f"(lo), "f"(hi)); return r;
}
__device__ __forceinline__ void unpack2(ull v, float& lo, float& hi) {
    asm("mov.b64 {%0, %1}, %2;" : "=f"(lo), "=f"(hi) : "l"(v));
}
__device__ __forceinline__ void fma2(ull& d, ull a, ull b) {
    asm("fma.rn.f32x2 %0, %1, %2, %0;" : "+l"(d) : "l"(a), "l"(b));
}
__device__ __forceinline__ ull lds64(const float* p) {
    ull v; unsigned sa = (unsigned)__cvta_generic_to_shared(p);
    asm("ld.shared.b64 %0, [%1];" : "=l"(v) : "r"(sa));
    return v;
}

// ---------------- dummy (ncu skip-count steering) -----------------------------
__global__ void dummy_kernel() {}

// ---------------- GEMM1: g_sup1 = x @ W1  (N x 1433 @ 1433 x 40) --------------
// Block 256 thr, tile 128 rows x 40 cols, BK=32.
// Thread (ty=tid/8, tx=tid%8) owns rows ty*4..+3 (as 2 f32x2 pairs) x 5 cols.
// Inner loop uses packed fma.rn.f32x2: 10 FMA2 = 40 lane-FMAs per k-step.
__global__ void __launch_bounds__(256) gemm1_kernel(
    const float* __restrict__ x, const float* __restrict__ W1)
{
    __shared__ float xsT[32][130];  // [k][r], stride 130 (even for LDS.64 align)
    __shared__ float ws[32][NHID];

    const int tid = threadIdx.x;
    const int ty4 = (tid >> 3) << 2;   // row offset 0..124 step 4
    const int tx5 = (tid & 7) * 5;     // col offset 0..35 step 5
    const int row0 = blockIdx.x * 128;

    ull acc[2][5];
    #pragma unroll
    for (int i = 0; i < 2; i++)
        #pragma unroll
        for (int j = 0; j < 5; j++) acc[i][j] = 0ull;

    for (int k0 = 0; k0 < NFEAT; k0 += 32) {
        // fill xsT (transposed): lanes -> consecutive gk (coalesced global)
        #pragma unroll
        for (int i = 0; i < 16; i++) {
            int idx = tid + i * 256;
            int r = idx >> 5, k = idx & 31;
            int gr = row0 + r, gk = k0 + k;
            float v = 0.0f;
            if (gr < N_NODES && gk < NFEAT) v = x[(size_t)gr * NFEAT + gk];
            xsT[k][r] = v;
        }
        // fill ws: 32 x 40
        #pragma unroll
        for (int i = 0; i < 5; i++) {
            int idx = tid + i * 256;
            int k = idx / NHID, c = idx % NHID;
            int gk = k0 + k;
            ws[k][c] = (gk < NFEAT) ? W1[gk * NHID + c] : 0.0f;
        }
        __syncthreads();

        #pragma unroll
        for (int k = 0; k < 32; k++) {
            ull A01 = lds64(&xsT[k][ty4]);       // (row ty4, row ty4+1)
            ull A23 = lds64(&xsT[k][ty4 + 2]);   // (row ty4+2, row ty4+3)
            #pragma unroll
            for (int j = 0; j < 5; j++) {
                float b = ws[k][tx5 + j];
                ull B = pack2(b, b);
                fma2(acc[0][j], A01, B);
                fma2(acc[1][j], A23, B);
            }
        }
        __syncthreads();
    }

    #pragma unroll
    for (int i = 0; i < 2; i++) {
        int gr0 = row0 + ty4 + i * 2;
        #pragma unroll
        for (int j = 0; j < 5; j++) {
            float lo, hi;
            unpack2(acc[i][j], lo, hi);
            if (gr0 < N_NODES)     g_sup1[(size_t)gr0 * NHID + tx5 + j]       = lo;
            if (gr0 + 1 < N_NODES) g_sup1[(size_t)(gr0 + 1) * NHID + tx5 + j] = hi;
        }
    }
}

// ---------------- scatter layer 1: agg1[dst] += sup1[src] * w ----------------
__global__ void scatter1_kernel(const int* __restrict__ src, const int* __restrict__ dst,
                                const float* __restrict__ ew, int E)
{
    int e = blockIdx.x * blockDim.x + threadIdx.x;
    if (e >= E) return;
    int s = src[e], d = dst[e];
    float w = ew[e];
    const float4* sp = (const float4*)(g_sup1 + (size_t)s * NHID);
    float*        ap = g_agg1 + (size_t)d * NHID;
    #pragma unroll
    for (int c = 0; c < NHID / 4; c++) {
        float4 v = __ldg(sp + c);
        red_add_v4(ap + c * 4, v.x * w, v.y * w, v.z * w, v.w * w);
    }
}

// ---------------- GEMM2 fused: sup2 = (relu(agg1+b1)*dropmask) @ W2 ----------
__global__ void __launch_bounds__(256) gemm2_kernel(
    const float* __restrict__ W2, const float* __restrict__ b1,
    const float* __restrict__ mask)
{
    __shared__ float w2s[NHID * NCLASS];  // 280
    __shared__ float b1s[NHID];
    for (int i = threadIdx.x; i < NHID * NCLASS; i += 256) w2s[i] = W2[i];
    if (threadIdx.x < NHID) b1s[threadIdx.x] = b1[threadIdx.x];
    __syncthreads();

    int n = blockIdx.x * blockDim.x + threadIdx.x;
    if (n >= N_NODES) return;

    const float4* ap = (const float4*)(g_agg1 + (size_t)n * NHID);
    const float4* mp = (const float4*)(mask + (size_t)n * NHID);
    float h[NHID];
    #pragma unroll
    for (int i = 0; i < NHID / 4; i++) {
        float4 v = ap[i];
        float4 m = __ldg(mp + i);
        h[i * 4 + 0] = (m.x > 0.5f) ? fmaxf(v.x + b1s[i * 4 + 0], 0.0f) * 2.0f : 0.0f;
        h[i * 4 + 1] = (m.y > 0.5f) ? fmaxf(v.y + b1s[i * 4 + 1], 0.0f) * 2.0f : 0.0f;
        h[i * 4 + 2] = (m.z > 0.5f) ? fmaxf(v.z + b1s[i * 4 + 2], 0.0f) * 2.0f : 0.0f;
        h[i * 4 + 3] = (m.w > 0.5f) ? fmaxf(v.w + b1s[i * 4 + 3], 0.0f) * 2.0f : 0.0f;
    }
    float acc[NCLASS];
    #pragma unroll
    for (int c = 0; c < NCLASS; c++) acc[c] = 0.0f;
    #pragma unroll
    for (int k = 0; k < NHID; k++) {
        float hv = h[k];
        #pragma unroll
        for (int c = 0; c < NCLASS; c++) acc[c] += hv * w2s[k * NCLASS + c];
    }
    float* op = g_sup2 + (size_t)n * NC_PAD;
    #pragma unroll
    for (int c = 0; c < NCLASS; c++) op[c] = acc[c];
    op[NCLASS] = 0.0f;  // pad
}

// ---------------- scatter layer 2: agg2[dst] += sup2[src] * w ----------------
__global__ void scatter2_kernel(const int* __restrict__ src, const int* __restrict__ dst,
                                const float* __restrict__ ew, int E)
{
    int e = blockIdx.x * blockDim.x + threadIdx.x;
    if (e >= E) return;
    int s = src[e], d = dst[e];
    float w = ew[e];
    const float4* sp = (const float4*)(g_sup2 + (size_t)s * NC_PAD);
    float*        ap = g_agg2 + (size_t)d * NC_PAD;
    float4 v0 = __ldg(sp + 0);
    float4 v1 = __ldg(sp + 1);
    red_add_v4(ap + 0, v0.x * w, v0.y * w, v0.z * w, v0.w * w);
    red_add_v4(ap + 4, v1.x * w, v1.y * w, v1.z * w, v1.w * w);
}

// ---------------- log_softmax(agg2 + b2) -> out ------------------------------
__global__ void logsoftmax_kernel(const float* __restrict__ b2, float* __restrict__ out)
{
    int n = blockIdx.x * blockDim.x + threadIdx.x;
    if (n >= N_NODES) return;
    const float* ap = g_agg2 + (size_t)n * NC_PAD;
    float z[NCLASS];
    float m = -1e30f;
    #pragma unroll
    for (int c = 0; c < NCLASS; c++) {
        z[c] = ap[c] + __ldg(b2 + c);
        m = fmaxf(m, z[c]);
    }
    float s = 0.0f;
    #pragma unroll
    for (int c = 0; c < NCLASS; c++) s += __expf(z[c] - m);
    float lse = m + __logf(s);
    #pragma unroll
    for (int c = 0; c < NCLASS; c++) out[n * NCLASS + c] = z[c] - lse;
}

// ---------------- launch -----------------------------------------------------
extern "C" void kernel_launch(void* const* d_in, const int* in_sizes, int n_in,
                              void* d_out, int out_size)
{
    const float* x    = (const float*)d_in[0];
    const int*   src  = (const int*)  d_in[1];
    const int*   dst  = (const int*)  d_in[2];
    const float* ew   = (const float*)d_in[3];
    const float* W1   = (const float*)d_in[4];
    const float* b1   = (const float*)d_in[5];
    const float* W2   = (const float*)d_in[6];
    const float* b2   = (const float*)d_in[7];
    const float* mask = (const float*)d_in[8];
    float* out = (float*)d_out;

    const int E = in_sizes[1];

    void* agg1_ptr = nullptr;
    void* agg2_ptr = nullptr;
    cudaGetSymbolAddress(&agg1_ptr, g_agg1);
    cudaGetSymbolAddress(&agg2_ptr, g_agg2);
    cudaMemsetAsync(agg1_ptr, 0, (size_t)N_NODES * NHID * sizeof(float), 0);
    cudaMemsetAsync(agg2_ptr, 0, (size_t)N_NODES * NC_PAD * sizeof(float), 0);

    // ncu -s 5 -c 1 counts memsets as launches: 2 memsets + 2 dummies puts
    // the captured launch (index 5) on scatter1_kernel.
    dummy_kernel<<<1, 1>>>();
    dummy_kernel<<<1, 1>>>();

    gemm1_kernel<<<(N_NODES + 127) / 128, 256>>>(x, W1);
    scatter1_kernel<<<(E + 255) / 256, 256>>>(src, dst, ew, E);
    gemm2_kernel<<<(N_NODES + 255) / 256, 256>>>(W2, b1, mask);
    scatter2_kernel<<<(E + 255) / 256, 256>>>(src, dst, ew, E);
    logsoftmax_kernel<<<(N_NODES + 255) / 256, 256>>>(b2, out);
}

// round 5
// speedup vs baseline: 1.8184x; 1.1397x over previous
#include <cuda_runtime.h>
#include <cuda_bf16.h>

#define N_NODES 100000
#define NFEAT   1433
#define NHID    40
#define NCLASS  7
#define NC_PAD  8
#define E_MAX   3200000
#define SCAN_B  1024
#define SCAN_NBLK ((N_NODES + SCAN_B - 1) / SCAN_B)   // 98

typedef unsigned long long ull;

// ---------------- scratch (device globals; no allocation allowed) -------------
__device__ float g_sup1[N_NODES * NHID];     // x @ W1
__device__ float g_h1  [N_NODES * NHID];     // relu(agg1+b1)*drop
__device__ float g_sup2[N_NODES * NC_PAD];   // h1 @ W2 (padded)
__device__ int   g_counts[N_NODES];
__device__ int   g_rowptr[N_NODES + 1];
__device__ int   g_pos[N_NODES];
__device__ int   g_blocksum[SCAN_NBLK];
__device__ int   g_blockoff[SCAN_NBLK];
__device__ int2  g_csr_edge[E_MAX];          // (src, weight-bits) sorted by dst

// ---------------- helpers ----------------------------------------------------
__device__ __forceinline__ ull pack2(float lo, float hi) {
    ull r; asm("mov.b64 %0, {%1, %2};" : "=l"(r) : "f"(lo), "f"(hi)); return r;
}
__device__ __forceinline__ void unpack2(ull v, float& lo, float& hi) {
    asm("mov.b64 {%0, %1}, %2;" : "=f"(lo), "=f"(hi) : "l"(v));
}
__device__ __forceinline__ void fma2(ull& d, ull a, ull b) {
    asm("fma.rn.f32x2 %0, %1, %2, %0;" : "+l"(d) : "l"(a), "l"(b));
}
__device__ __forceinline__ ull lds64(const float* p) {
    ull v; unsigned sa = (unsigned)__cvta_generic_to_shared(p);
    asm("ld.shared.b64 %0, [%1];" : "=l"(v) : "r"(sa));
    return v;
}

// ---------------- CSR build ---------------------------------------------------
__global__ void hist_kernel(const int* __restrict__ dst, int E) {
    int e = blockIdx.x * blockDim.x + threadIdx.x;
    if (e < E) atomicAdd(&g_counts[dst[e]], 1);
}

// per-block exclusive scan; writes exclusive-within-block prefix + block sum
__global__ void __launch_bounds__(SCAN_B) scan_part_kernel() {
    __shared__ int sh[SCAN_B];
    int t = threadIdx.x;
    int i = blockIdx.x * SCAN_B + t;
    int v = (i < N_NODES) ? g_counts[i] : 0;
    sh[t] = v;
    __syncthreads();
    #pragma unroll
    for (int off = 1; off < SCAN_B; off <<= 1) {
        int a = (t >= off) ? sh[t - off] : 0;
        __syncthreads();
        sh[t] += a;
        __syncthreads();
    }
    if (i < N_NODES) g_rowptr[i] = sh[t] - v;       // exclusive within block
    if (t == SCAN_B - 1) g_blocksum[blockIdx.x] = sh[t];
}

__global__ void scan_top_kernel() {
    __shared__ int sh[128];
    int t = threadIdx.x;
    int v = (t < SCAN_NBLK) ? g_blocksum[t] : 0;
    sh[t] = v;
    __syncthreads();
    #pragma unroll
    for (int off = 1; off < 128; off <<= 1) {
        int a = (t >= off) ? sh[t - off] : 0;
        __syncthreads();
        sh[t] += a;
        __syncthreads();
    }
    if (t < SCAN_NBLK) g_blockoff[t] = sh[t] - v;   // exclusive
}

__global__ void scan_add_kernel(int E) {
    int i = blockIdx.x * blockDim.x + threadIdx.x;
    if (i < N_NODES) {
        int r = g_rowptr[i] + g_blockoff[i >> 10];
        g_rowptr[i] = r;
        g_pos[i] = r;
    }
    if (i == 0) g_rowptr[N_NODES] = E;
}

__global__ void fill_kernel(const int* __restrict__ src, const int* __restrict__ dst,
                            const float* __restrict__ ew, int E) {
    int e = blockIdx.x * blockDim.x + threadIdx.x;
    if (e >= E) return;
    int p = atomicAdd(&g_pos[dst[e]], 1);
    g_csr_edge[p] = make_int2(src[e], __float_as_int(ew[e]));
}

// ---------------- GEMM1: g_sup1 = x @ W1  (N x 1433 @ 1433 x 40) --------------
// 256 thr, tile 256 rows x 40 cols, BK=32. Thread owns 8 rows (4 f32x2) x 5 cols.
// B pre-duplicated as f32x2 in smem: per k-step 9 LDS.64 + 20 FMA2 = 80 lane-FMAs.
__global__ void __launch_bounds__(256) gemm1_kernel(
    const float* __restrict__ x, const float* __restrict__ W1)
{
    __shared__ __align__(16) float xsT[32][258];  // [k][r], stride 258 (even, 2-way store conf only)
    __shared__ ull wsd[32][NHID];                 // duplicated (b,b) pairs

    const int tid = threadIdx.x;
    const int ty8 = (tid >> 3) << 3;   // 0..248 step 8
    const int tx5 = (tid & 7) * 5;
    const int row0 = blockIdx.x * 256;

    ull acc[4][5];
    #pragma unroll
    for (int i = 0; i < 4; i++)
        #pragma unroll
        for (int j = 0; j < 5; j++) acc[i][j] = 0ull;

    for (int k0 = 0; k0 < NFEAT; k0 += 32) {
        // x tile: 256 rows x 32 k, transposed into xsT (coalesced LDG.128-ish)
        #pragma unroll
        for (int i = 0; i < 32; i++) {
            int idx = tid + i * 256;
            int r = idx >> 5, k = idx & 31;
            int gr = row0 + r, gk = k0 + k;
            float v = 0.0f;
            if (gr < N_NODES && gk < NFEAT) v = x[(size_t)gr * NFEAT + gk];
            xsT[k][r] = v;
        }
        // W tile 32 x 40, duplicated
        #pragma unroll
        for (int i = 0; i < 5; i++) {
            int idx = tid + i * 256;
            int k = idx / NHID, c = idx % NHID;
            int gk = k0 + k;
            float v = (gk < NFEAT) ? W1[gk * NHID + c] : 0.0f;
            wsd[k][c] = pack2(v, v);
        }
        __syncthreads();

        #pragma unroll
        for (int k = 0; k < 32; k++) {
            ull A0 = lds64(&xsT[k][ty8 + 0]);
            ull A1 = lds64(&xsT[k][ty8 + 2]);
            ull A2 = lds64(&xsT[k][ty8 + 4]);
            ull A3 = lds64(&xsT[k][ty8 + 6]);
            #pragma unroll
            for (int j = 0; j < 5; j++) {
                ull B = wsd[k][tx5 + j];
                fma2(acc[0][j], A0, B);
                fma2(acc[1][j], A1, B);
                fma2(acc[2][j], A2, B);
                fma2(acc[3][j], A3, B);
            }
        }
        __syncthreads();
    }

    #pragma unroll
    for (int i = 0; i < 4; i++) {
        int gr0 = row0 + ty8 + i * 2;
        #pragma unroll
        for (int j = 0; j < 5; j++) {
            float lo, hi;
            unpack2(acc[i][j], lo, hi);
            if (gr0 < N_NODES)     g_sup1[(size_t)gr0 * NHID + tx5 + j]       = lo;
            if (gr0 + 1 < N_NODES) g_sup1[(size_t)(gr0 + 1) * NHID + tx5 + j] = hi;
        }
    }
}

// ------- agg1 (warp/node CSR gather) fused with bias+relu+dropout -> g_h1 -----
__global__ void __launch_bounds__(256) agg1_kernel(
    const float* __restrict__ b1, const float* __restrict__ mask)
{
    int n = (blockIdx.x * blockDim.x + threadIdx.x) >> 5;
    int lane = threadIdx.x & 31;
    if (n >= N_NODES) return;
    int beg = g_rowptr[n], end = g_rowptr[n + 1];

    float acc0 = 0.0f, acc1 = 0.0f;
    #pragma unroll 1
    for (int e0 = beg; e0 < end; e0 += 4) {
        int2 ed[4];
        #pragma unroll
        for (int j = 0; j < 4; j++) {
            int idx = e0 + j;
            ed[j] = (idx < end) ? __ldg(&g_csr_edge[idx]) : make_int2(0, 0);
        }
        #pragma unroll
        for (int j = 0; j < 4; j++) {
            float w = __int_as_float(ed[j].y);
            const float* row = g_sup1 + (size_t)ed[j].x * NHID;
            acc0 = fmaf(w, __ldg(row + lane), acc0);
            if (lane < 8) acc1 = fmaf(w, __ldg(row + 32 + lane), acc1);
        }
    }
    // bias + relu + dropout (keep if mask > 0.5, scale x2)
    {
        float v = fmaxf(acc0 + __ldg(b1 + lane), 0.0f);
        float m = __ldg(mask + (size_t)n * NHID + lane);
        g_h1[(size_t)n * NHID + lane] = (m > 0.5f) ? v * 2.0f : 0.0f;
    }
    if (lane < 8) {
        int c = 32 + lane;
        float v = fmaxf(acc1 + __ldg(b1 + c), 0.0f);
        float m = __ldg(mask + (size_t)n * NHID + c);
        g_h1[(size_t)n * NHID + c] = (m > 0.5f) ? v * 2.0f : 0.0f;
    }
}

// ---------------- GEMM2: sup2 = h1 @ W2 (N x 40 @ 40 x 7, padded to 8) -------
__global__ void __launch_bounds__(256) gemm2_kernel(const float* __restrict__ W2)
{
    __shared__ float w2s[NHID * NCLASS];  // 280 > 256: strided
    for (int i = threadIdx.x; i < NHID * NCLASS; i += 256) w2s[i] = W2[i];
    __syncthreads();

    int n = blockIdx.x * blockDim.x + threadIdx.x;
    if (n >= N_NODES) return;

    const float4* hp = (const float4*)(g_h1 + (size_t)n * NHID);
    float h[NHID];
    #pragma unroll
    for (int i = 0; i < NHID / 4; i++) {
        float4 v = hp[i];
        h[i * 4 + 0] = v.x; h[i * 4 + 1] = v.y; h[i * 4 + 2] = v.z; h[i * 4 + 3] = v.w;
    }
    float acc[NCLASS];
    #pragma unroll
    for (int c = 0; c < NCLASS; c++) acc[c] = 0.0f;
    #pragma unroll
    for (int k = 0; k < NHID; k++) {
        float hv = h[k];
        #pragma unroll
        for (int c = 0; c < NCLASS; c++) acc[c] += hv * w2s[k * NCLASS + c];
    }
    float* op = g_sup2 + (size_t)n * NC_PAD;
    #pragma unroll
    for (int c = 0; c < NCLASS; c++) op[c] = acc[c];
    op[NCLASS] = 0.0f;  // pad (lane f=7 in agg2 reads this)
}

// ------- agg2 (warp/node, 4 edges x 8 feats) fused with bias + log_softmax ----
__global__ void __launch_bounds__(256) agg2_lsm_kernel(
    const float* __restrict__ b2, float* __restrict__ out)
{
    int n = (blockIdx.x * blockDim.x + threadIdx.x) >> 5;
    int lane = threadIdx.x & 31;
    if (n >= N_NODES) return;
    int beg = g_rowptr[n], end = g_rowptr[n + 1];
    int j = lane >> 3;      // edge sub-slot 0..3
    int f = lane & 7;       // feature 0..7 (7 = pad)

    float acc = 0.0f;
    #pragma unroll 1
    for (int e0 = beg; e0 < end; e0 += 4) {
        int idx = e0 + j;
        int2 ed = (idx < end) ? __ldg(&g_csr_edge[idx]) : make_int2(0, 0);
        float w = __int_as_float(ed.y);
        acc = fmaf(w, __ldg(g_sup2 + (size_t)ed.x * NC_PAD + f), acc);
    }
    // reduce the 4 edge sub-slots (xor 8, 16 stay within... cross 8-groups)
    acc += __shfl_xor_sync(0xFFFFFFFFu, acc, 8);
    acc += __shfl_xor_sync(0xFFFFFFFFu, acc, 16);

    // log_softmax over the 8-lane feature group (f=7 is pad, excluded)
    float z = acc + __ldg(b2 + ((f < NCLASS) ? f : 0));
    float m = (f < NCLASS) ? z : -1e30f;
    m = fmaxf(m, __shfl_xor_sync(0xFFFFFFFFu, m, 1));
    m = fmaxf(m, __shfl_xor_sync(0xFFFFFFFFu, m, 2));
    m = fmaxf(m, __shfl_xor_sync(0xFFFFFFFFu, m, 4));
    float ex = (f < NCLASS) ? __expf(z - m) : 0.0f;
    float s = ex;
    s += __shfl_xor_sync(0xFFFFFFFFu, s, 1);
    s += __shfl_xor_sync(0xFFFFFFFFu, s, 2);
    s += __shfl_xor_sync(0xFFFFFFFFu, s, 4);
    float lse = m + __logf(s);
    if (f < NCLASS && j == 0)
        out[(size_t)n * NCLASS + f] = z - lse;
}

// ---------------- launch -----------------------------------------------------
extern "C" void kernel_launch(void* const* d_in, const int* in_sizes, int n_in,
                              void* d_out, int out_size)
{
    const float* x    = (const float*)d_in[0];
    const int*   src  = (const int*)  d_in[1];
    const int*   dst  = (const int*)  d_in[2];
    const float* ew   = (const float*)d_in[3];
    const float* W1   = (const float*)d_in[4];
    const float* b1   = (const float*)d_in[5];
    const float* W2   = (const float*)d_in[6];
    const float* b2   = (const float*)d_in[7];
    const float* mask = (const float*)d_in[8];
    float* out = (float*)d_out;

    const int E = in_sizes[1];

    void* counts_ptr = nullptr;
    cudaGetSymbolAddress(&counts_ptr, g_counts);
    // launch index (ncu -s 5 -c 1):                                    idx
    cudaMemsetAsync(counts_ptr, 0, N_NODES * sizeof(int), 0);       //  0
    hist_kernel<<<(E + 255) / 256, 256>>>(dst, E);                  //  1
    scan_part_kernel<<<SCAN_NBLK, SCAN_B>>>();                      //  2
    scan_top_kernel<<<1, 128>>>();                                  //  3
    scan_add_kernel<<<(N_NODES + 255) / 256, 256>>>(E);             //  4
    gemm1_kernel<<<(N_NODES + 255) / 256, 256>>>(x, W1);            //  5  <- profiled
    fill_kernel<<<(E + 255) / 256, 256>>>(src, dst, ew, E);         //  6
    agg1_kernel<<<(N_NODES * 32 + 255) / 256, 256>>>(b1, mask);     //  7
    gemm2_kernel<<<(N_NODES + 255) / 256, 256>>>(W2);               //  8
    agg2_lsm_kernel<<<(N_NODES * 32 + 255) / 256, 256>>>(b2, out);  //  9
}